// round 17
// baseline (speedup 1.0000x reference)
#include <cuda_runtime.h>
#include <math.h>

#define BB 64        // batch
#define TT 512       // seq len
#define HH 256       // hidden
#define G4 1024      // 4*H
#define NCLS 20
#define CLU 8        // cluster size = jgrp count

// Scratch (static device globals — no runtime allocation)
__device__ float g_xz[(size_t)BB * TT * G4];   // 128 MB
__device__ float g_hfin[BB * HH];              // final h_T

// ---------------------------------------------------------------------------
// helpers
// ---------------------------------------------------------------------------
__device__ __forceinline__ unsigned long long ffma2(unsigned long long a,
                                                    unsigned long long b,
                                                    unsigned long long c) {
    unsigned long long d;
    asm("fma.rn.f32x2 %0, %1, %2, %3;" : "=l"(d) : "l"(a), "l"(b), "l"(c));
    return d;
}
__device__ __forceinline__ unsigned long long pack2(float lo, float hi) {
    unsigned long long d;
    asm("mov.b64 %0, {%1, %2};" : "=l"(d) : "f"(lo), "f"(hi));
    return d;
}
__device__ __forceinline__ void unpack2(unsigned long long v, float& lo, float& hi) {
    asm("mov.b64 {%0, %1}, %2;" : "=f"(lo), "=f"(hi) : "l"(v));
}
__device__ __forceinline__ float sum2(unsigned long long v) {
    float lo, hi;
    asm("mov.b64 {%0, %1}, %2;" : "=f"(lo), "=f"(hi) : "l"(v));
    return lo + hi;
}
__device__ __forceinline__ float tanh_ap(float x) {
    float y;
    asm("tanh.approx.f32 %0, %1;" : "=f"(y) : "f"(x));
    return y;
}
__device__ __forceinline__ float sigm_ap(float x) {
    return fmaf(0.5f, tanh_ap(0.5f * x), 0.5f);
}
__device__ __forceinline__ void st_dsmem_f32(unsigned local_addr, int rank, float v) {
    unsigned rem;
    asm volatile("mapa.shared::cluster.u32 %0, %1, %2;"
                 : "=r"(rem) : "r"(local_addr), "r"(rank));
    asm volatile("st.shared::cluster.f32 [%0], %1;" :: "r"(rem), "f"(v));
}
__device__ __forceinline__ void st_dsmem_u32(unsigned local_addr, int rank, unsigned v) {
    unsigned rem;
    asm volatile("mapa.shared::cluster.u32 %0, %1, %2;"
                 : "=r"(rem) : "r"(local_addr), "r"(rank));
    asm volatile("st.shared::cluster.u32 [%0], %1;" :: "r"(rem), "r"(v));
}
__device__ __forceinline__ unsigned lds_acq(unsigned addr) {
    unsigned v;
    asm volatile("ld.acquire.cluster.shared::cta.u32 %0, [%1];"
                 : "=r"(v) : "r"(addr));
    return v;
}

// ---------------------------------------------------------------------------
// Phase A: xz[b,t,:] = emb[x[b,t]] @ W + bias      (M=32768, K=256, N=1024)
// 128x128 tile, 256 threads, 8x8 micro-tile, packed f32x2 math. (R16)
// ---------------------------------------------------------------------------
__global__ __launch_bounds__(256) void phaseA_kernel(
    const int* __restrict__ x, const float* __restrict__ emb,
    const float* __restrict__ W, const float* __restrict__ bias)
{
    __shared__ float As[16][136];
    __shared__ float Bs[16][136];
    __shared__ int ridx[128];

    const int tid = threadIdx.x;
    const int bx = blockIdx.x;   // 0..7
    const int by = blockIdx.y;   // 0..255

    if (tid < 128) ridx[tid] = x[by * 128 + tid];
    __syncthreads();

    const int tx = tid & 15;
    const int ty = tid >> 4;

    unsigned long long acc2[8][4];
#pragma unroll
    for (int i = 0; i < 8; i++)
#pragma unroll
        for (int j = 0; j < 4; j++) acc2[i][j] = 0ull;

    const int ar  = tid >> 1;
    const int akq = (tid & 1) << 3;
    const int bkk = tid >> 4;
    const int bc8 = (tid & 15) << 3;

    for (int k0 = 0; k0 < 256; k0 += 16) {
        {
            const float* ap = emb + (size_t)ridx[ar] * 256 + k0 + akq;
            float4 va = *(const float4*)(ap);
            float4 vb = *(const float4*)(ap + 4);
            As[akq + 0][ar] = va.x; As[akq + 1][ar] = va.y;
            As[akq + 2][ar] = va.z; As[akq + 3][ar] = va.w;
            As[akq + 4][ar] = vb.x; As[akq + 5][ar] = vb.y;
            As[akq + 6][ar] = vb.z; As[akq + 7][ar] = vb.w;
            const float* bp = W + (size_t)(k0 + bkk) * G4 + bx * 128 + bc8;
            *(float4*)&Bs[bkk][bc8]     = *(const float4*)(bp);
            *(float4*)&Bs[bkk][bc8 + 4] = *(const float4*)(bp + 4);
        }
        __syncthreads();
#pragma unroll
        for (int k = 0; k < 16; k++) {
            float4 a0 = *(const float4*)&As[k][ty << 3];
            float4 a1 = *(const float4*)&As[k][(ty << 3) + 4];
            ulonglong2 bb0 = *(const ulonglong2*)&Bs[k][tx << 3];
            ulonglong2 bb1 = *(const ulonglong2*)&Bs[k][(tx << 3) + 4];
            float a[8] = {a0.x, a0.y, a0.z, a0.w, a1.x, a1.y, a1.z, a1.w};
#pragma unroll
            for (int i = 0; i < 8; i++) {
                unsigned long long ad = pack2(a[i], a[i]);
                acc2[i][0] = ffma2(ad, bb0.x, acc2[i][0]);
                acc2[i][1] = ffma2(ad, bb0.y, acc2[i][1]);
                acc2[i][2] = ffma2(ad, bb1.x, acc2[i][2]);
                acc2[i][3] = ffma2(ad, bb1.y, acc2[i][3]);
            }
        }
        __syncthreads();
    }

    const int colbase = bx * 128 + (tx << 3);
    float4 bv0 = *(const float4*)(bias + colbase);
    float4 bv1 = *(const float4*)(bias + colbase + 4);
#pragma unroll
    for (int i = 0; i < 8; i++) {
        int row = by * 128 + (ty << 3) + i;
        float o0, o1, o2, o3, o4, o5, o6, o7;
        unpack2(acc2[i][0], o0, o1);
        unpack2(acc2[i][1], o2, o3);
        unpack2(acc2[i][2], o4, o5);
        unpack2(acc2[i][3], o6, o7);
        float4 w0 = make_float4(o0 + bv0.x, o1 + bv0.y, o2 + bv0.z, o3 + bv0.w);
        float4 w1 = make_float4(o4 + bv1.x, o5 + bv1.y, o6 + bv1.z, o7 + bv1.w);
        float* op = g_xz + (size_t)row * G4 + colbase;
        *(float4*)(op)     = w0;
        *(float4*)(op + 4) = w1;
    }
}

// ---------------------------------------------------------------------------
// Phase B: 512 LSTM steps. 16 clusters (bgrp) x 8 CTAs (jgrp/rank).
// U in REGISTERS (8gc x 16k per thread). EXCHANGE: producers PUSH h values
// into all 8 peers' 4-deep smem ring via st.shared::cluster; fence.cluster +
// 128-bar; one tag word per peer (monotone step counter). Consumers spin on
// the LOCAL smem tag (ld.acquire.cluster) — no L2 round trips, no cluster
// barrier, no mbarrier in the loop. Compute/fold/combine identical to R15.
// ---------------------------------------------------------------------------
#define KROW 320                     // 16 k-blocks * 20 floats (bank-optimal)
#define HSLOT (4 * KROW)             // one ring slot: 4 batches
#define HS_OFF 0                     // [4][HSLOT] ring
#define PART_OFF (4 * HSLOT)         // skewed scratch
#define TAG_OFF (PART_OFF + 8736)    // 8 tag words (+pad)
#define SMEM_FLOATS (TAG_OFF + 16)
#define SMEM_B (SMEM_FLOATS * 4)

extern __shared__ float sdyn[];

__global__ __launch_bounds__(256, 1) __cluster_dims__(CLU, 1, 1)
void phaseB_kernel(const float* __restrict__ U)
{
    float* hs   = sdyn + HS_OFF;       // [4][4][KROW] ring of h stages
    float* part = sdyn + PART_OFF;

    const int tid  = threadIdx.x;      // 256
    const int jgrp = blockIdx.x;       // 0..7 = cluster rank (col group)
    const int bgrp = blockIdx.y;       // 0..15 (4 batches)

    const int ks    = tid & 15;        // k split 0..15 (16 k each)
    const int gcblk = tid >> 4;        // 0..15 (8 gate-cols each)
    const int wid   = tid >> 5;        // 0..7

    const unsigned smem_base = (unsigned)__cvta_generic_to_shared(sdyn);

    // ---- load this thread's U tile into registers (one-time) ----
    unsigned long long ureg[8][8];     // [t8][k-pair p], k = ks*16 + 2p
    {
        const int gc0  = gcblk * 8;
        const int colb = (gc0 >> 5) * HH + jgrp * 32 + (gc0 & 31);
#pragma unroll
        for (int p = 0; p < 8; p++) {
            const float* r0 = U + (size_t)(ks * 16 + 2 * p) * G4 + colb;
            const float* r1 = r0 + G4;
            float4 a0 = *(const float4*)(r0);
            float4 a1 = *(const float4*)(r0 + 4);
            float4 b0 = *(const float4*)(r1);
            float4 b1 = *(const float4*)(r1 + 4);
            ureg[0][p] = pack2(a0.x, b0.x);
            ureg[1][p] = pack2(a0.y, b0.y);
            ureg[2][p] = pack2(a0.z, b0.z);
            ureg[3][p] = pack2(a0.w, b0.w);
            ureg[4][p] = pack2(a1.x, b1.x);
            ureg[5][p] = pack2(a1.y, b1.y);
            ureg[6][p] = pack2(a1.z, b1.z);
            ureg[7][p] = pack2(a1.w, b1.w);
        }
    }

    // zero full ring (slot 0 = h_0 = 0) and tags
    for (int i = tid; i < 4 * HSLOT; i += 256) hs[i] = 0.f;
    if (tid < 16) *(unsigned*)(sdyn + TAG_OFF + tid) = 0u;
    __syncthreads();
    // peers' smem/tags ready before any push
    asm volatile("barrier.cluster.arrive.aligned;" ::: "memory");
    asm volatile("barrier.cluster.wait.aligned;" ::: "memory");

    // gate-thread params (tid < 128): (bl 0..3, jl 0..31)
    const int bl = tid >> 5;
    const int jl = tid & 31;
    const int b  = bgrp * 4 + bl;
    const int j  = jgrp * 32 + jl;
    float c = 0.f;
    const float* xzp = g_xz + (size_t)b * TT * G4 + j;

    // producer push base (byte offset within any rank's smem, slot added/step)
    const unsigned pushb =
        smem_base + 4u * (unsigned)(HS_OFF + bl * KROW + (j >> 4) * 20 + (j & 15));
    const unsigned tag_my = smem_base + 4u * (unsigned)(TAG_OFF + jgrp);
    const unsigned tag_w  = smem_base + 4u * (unsigned)(TAG_OFF + wid);

    for (int t = 0; t < TT; t++) {
        // xz prefetch (gate threads only; issued before any wait)
        float a0 = 0.f, a1 = 0.f, a2 = 0.f, a3 = 0.f;
        if (tid < 128) {
            const float* xr = xzp + (size_t)t * G4;
            a0 = __ldg(xr + 0 * HH);
            a1 = __ldg(xr + 1 * HH);
            a2 = __ldg(xr + 2 * HH);
            a3 = __ldg(xr + 3 * HH);
        }

        // wait for producer wid's h_t pushes (local smem tag, acquire)
        if (t > 0) {
            while (lds_acq(tag_w) < (unsigned)t) { }
        }
        __syncthreads();   // A: all 8 tags seen -> slot (t&3) complete

        // ---- main tile: 4b x 8gc x 16k, U from registers ----
        const float* hsl = hs + (t & 3) * HSLOT;
        const ulonglong2* hp0 = (const ulonglong2*)(hsl + 0 * KROW + ks * 20);
        const ulonglong2* hp1 = (const ulonglong2*)(hsl + 1 * KROW + ks * 20);
        const ulonglong2* hp2 = (const ulonglong2*)(hsl + 2 * KROW + ks * 20);
        const ulonglong2* hp3 = (const ulonglong2*)(hsl + 3 * KROW + ks * 20);

        unsigned long long acc[32];
#pragma unroll
        for (int q = 0; q < 32; q++) acc[q] = 0ull;

#pragma unroll
        for (int iter = 0; iter < 4; iter++) {
            ulonglong2 h0 = hp0[iter];
            ulonglong2 h1 = hp1[iter];
            ulonglong2 h2 = hp2[iter];
            ulonglong2 h3 = hp3[iter];
#pragma unroll
            for (int t8 = 0; t8 < 8; t8++) {
                unsigned long long ux = ureg[t8][2 * iter];
                unsigned long long uy = ureg[t8][2 * iter + 1];
                acc[0 * 8 + t8] = ffma2(h0.x, ux, acc[0 * 8 + t8]);
                acc[0 * 8 + t8] = ffma2(h0.y, uy, acc[0 * 8 + t8]);
                acc[1 * 8 + t8] = ffma2(h1.x, ux, acc[1 * 8 + t8]);
                acc[1 * 8 + t8] = ffma2(h1.y, uy, acc[1 * 8 + t8]);
                acc[2 * 8 + t8] = ffma2(h2.x, ux, acc[2 * 8 + t8]);
                acc[2 * 8 + t8] = ffma2(h2.y, uy, acc[2 * 8 + t8]);
                acc[3 * 8 + t8] = ffma2(h3.x, ux, acc[3 * 8 + t8]);
                acc[3 * 8 + t8] = ffma2(h3.y, uy, acc[3 * 8 + t8]);
            }
        }

        // fold + write skewed partials: addr = (b*128 + gc)*17 + b*8 + ks
#pragma unroll
        for (int i = 0; i < 4; i++) {
            int base = (i * 128 + gcblk * 8) * 17 + i * 8 + ks;
#pragma unroll
            for (int t8 = 0; t8 < 8; t8++)
                part[base + t8 * 17] = sum2(acc[i * 8 + t8]);
        }
        __syncthreads();   // B: partials visible

        if (tid < 128) {
            float z[4];
#pragma unroll
            for (int g = 0; g < 4; g++) {
                int base = (bl * 128 + g * 32 + jl) * 17 + bl * 8;
                float s0 = part[base + 0] + part[base + 1];
                float s1 = part[base + 2] + part[base + 3];
                float s2 = part[base + 4] + part[base + 5];
                float s3 = part[base + 6] + part[base + 7];
                float s4 = part[base + 8] + part[base + 9];
                float s5 = part[base + 10] + part[base + 11];
                float s6 = part[base + 12] + part[base + 13];
                float s7 = part[base + 14] + part[base + 15];
                z[g] = ((s0 + s1) + (s2 + s3)) + ((s4 + s5) + (s6 + s7));
            }
            float z0 = a0 + z[0];
            float z1 = a1 + z[1];
            float z2 = a2 + z[2];
            float z3 = a3 + z[3];
            // gates (order i, f, g, o)
            float ig = sigm_ap(z0);
            float fg = sigm_ap(z1);
            float gg = tanh_ap(z2);
            float og = sigm_ap(z3);
            c = fmaf(fg, c, ig * gg);
            float hn = og * tanh_ap(c);
            // push h_{t+1}(b, j) into all 8 ranks' ring slot (t+1)&3
            unsigned dst = pushb + 4u * (unsigned)(((t + 1) & 3) * HSLOT);
#pragma unroll
            for (int r = 0; r < CLU; r++) st_dsmem_f32(dst, r, hn);
            if (t == TT - 1) g_hfin[b * HH + j] = hn;
            // make pushes cluster-visible, then publish tag to all ranks
            asm volatile("fence.acq_rel.cluster;" ::: "memory");
            asm volatile("bar.sync 1, 128;" ::: "memory");
            if (tid == 0) {
#pragma unroll
                for (int r = 0; r < CLU; r++)
                    st_dsmem_u32(tag_my, r, (unsigned)(t + 1));
            }
        }
    }

    // no CTA may exit while peers could still push into its smem
    asm volatile("barrier.cluster.arrive.aligned;" ::: "memory");
    asm volatile("barrier.cluster.wait.aligned;" ::: "memory");
}

// ---------------------------------------------------------------------------
// Phase C: logits = h_T @ Wd + bd; softmax. One warp per batch row.
// ---------------------------------------------------------------------------
__global__ __launch_bounds__(32) void phaseC_kernel(
    const float* __restrict__ Wd, const float* __restrict__ bd,
    float* __restrict__ out)
{
    const int b = blockIdx.x;
    const int lane = threadIdx.x;
    const float* h = g_hfin + b * HH;

    float v = 0.f;
    if (lane < NCLS) {
#pragma unroll 8
        for (int k = 0; k < HH; k++)
            v = fmaf(h[k], Wd[k * NCLS + lane], v);
        v += bd[lane];
    }
    float m = (lane < NCLS) ? v : -1e30f;
#pragma unroll
    for (int o = 16; o; o >>= 1) m = fmaxf(m, __shfl_xor_sync(0xffffffffu, m, o));
    float e = (lane < NCLS) ? __expf(v - m) : 0.f;
    float s = e;
#pragma unroll
    for (int o = 16; o; o >>= 1) s += __shfl_xor_sync(0xffffffffu, s, o);
    if (lane < NCLS) out[b * NCLS + lane] = e / s;
}

// ---------------------------------------------------------------------------
extern "C" void kernel_launch(void* const* d_in, const int* in_sizes, int n_in,
                              void* d_out, int out_size)
{
    const int*   x    = (const int*)d_in[0];
    const float* emb  = (const float*)d_in[1];
    const float* W    = (const float*)d_in[2];
    const float* U    = (const float*)d_in[3];
    const float* bias = (const float*)d_in[4];
    const float* Wd   = (const float*)d_in[5];
    const float* bd   = (const float*)d_in[6];
    float* out = (float*)d_out;

    static bool inited = false;
    if (!inited) {
        cudaFuncSetAttribute(phaseB_kernel,
                             cudaFuncAttributeMaxDynamicSharedMemorySize, SMEM_B);
        inited = true;
    }

    phaseA_kernel<<<dim3(8, 256), 256>>>(x, emb, W, bias);
    phaseB_kernel<<<dim3(CLU, 16), 256, SMEM_B>>>(U);
    phaseC_kernel<<<BB, 32>>>(Wd, bd, out);
}